// round 2
// baseline (speedup 1.0000x reference)
#include <cuda_runtime.h>

// Problem constants
#define BATCH 16
#define LP    2048
#define LQ    2048
#define HID   1024

// GEMM tiling
#define BM 128
#define BN 128
#define BK 16

// Scratch (allocation-free: __device__ globals)
__device__ float g_transq[(size_t)BATCH * LQ * HID];   // 134 MB
__device__ float g_att   [(size_t)BATCH * LP * LQ];    // 268 MB
__device__ float g_attvec[(size_t)BATCH * LP * HID];   // 134 MB

// ---------------- f32x2 packed-FMA helpers (FFMA2, sm_10x) ----------------
__device__ __forceinline__ unsigned long long pack2(float lo, float hi) {
    unsigned long long r;
    asm("mov.b64 %0, {%1, %2};" : "=l"(r) : "f"(lo), "f"(hi));
    return r;
}
__device__ __forceinline__ unsigned long long fma2(unsigned long long a,
                                                   unsigned long long b,
                                                   unsigned long long c) {
    unsigned long long d;
    asm("fma.rn.f32x2 %0, %1, %2, %3;" : "=l"(d) : "l"(a), "l"(b), "l"(c));
    return d;
}
__device__ __forceinline__ float2 unpack2(unsigned long long v) {
    float2 f;
    asm("mov.b64 {%0, %1}, %2;" : "=f"(f.x), "=f"(f.y) : "l"(v));
    return f;
}

// ---------------------------------------------------------------------------
// Generic tiled SGEMM:
//   C[m,n] = sum_k A[m,k] * B'[.,.]   (+bias[n]) (+ReLU)
//   A is always row-major [M,K] (k contiguous).
//   BKM=true : B is [N,K] row-major (k contiguous)  -> C = A * B^T
//   BKM=false: B is [K,N] row-major (n contiguous)  -> C = A * B
// Batched via blockIdx.z with element strides sA/sB/sC.
// Requires M%128==0, N%128==0, K%16==0.
// ---------------------------------------------------------------------------
template <bool BKM, bool BIAS, bool RELU>
__global__ __launch_bounds__(256)
void sgemm_kernel(const float* __restrict__ A, const float* __restrict__ Bg,
                  const float* __restrict__ bias, float* __restrict__ C,
                  int M, int N, int K,
                  long long sA, long long sB, long long sC)
{
    A  += sA * (long long)blockIdx.z;
    Bg += sB * (long long)blockIdx.z;
    C  += sC * (long long)blockIdx.z;

    const int m0 = blockIdx.y * BM;
    const int n0 = blockIdx.x * BN;
    const int tid = threadIdx.x;

    __shared__ float As[2][BK][BM];
    __shared__ float Bs[2][BK][BN];

    // ---- global loader mapping ----
    // A: 256 threads load 128 rows x 16 k as 2 float4 each.
    const int a_row = tid >> 2;          // 0..63 (and +64)
    const int a_kv  = (tid & 3) << 2;    // 0,4,8,12
    const float* Aptr = A + (long long)(m0 + a_row) * K + a_kv;

    // B loaders
    int b_row, b_col;
    if (BKM) { b_row = tid >> 2; b_col = (tid & 3) << 2; }   // N-row, K-col
    else     { b_row = tid >> 5; b_col = (tid & 31) << 2; }  // K-row, N-col
    const float* Bptr;
    if (BKM) Bptr = Bg + (long long)(n0 + b_row) * K + b_col;
    else     Bptr = Bg + (long long)b_row * N + (n0 + b_col);

    // ---- compute fragment mapping ----
    const int tx = tid & 15;             // n direction
    const int ty = tid >> 4;             // m direction
    // thread columns: {n0+tx*4 .. +3} and {n0+64+tx*4 .. +3}
    // thread rows:    {m0+ty*4 .. +3} and {m0+64+ty*4 .. +3}

    unsigned long long acc[8][4];
    #pragma unroll
    for (int i = 0; i < 8; i++)
        #pragma unroll
        for (int j = 0; j < 4; j++) acc[i][j] = 0ULL;

    const int nk = K / BK;

    float4 aR0, aR1, bR0, bR1;

    // ---- prologue: tile 0 ----
    aR0 = *(const float4*)(Aptr);
    aR1 = *(const float4*)(Aptr + 64LL * K);
    if (BKM) {
        bR0 = *(const float4*)(Bptr);
        bR1 = *(const float4*)(Bptr + 64LL * K);
    } else {
        bR0 = *(const float4*)(Bptr);
        bR1 = *(const float4*)(Bptr + 8LL * N);
    }
    // store tile 0 (A transposed, B per layout)
    As[0][a_kv + 0][a_row] = aR0.x;  As[0][a_kv + 1][a_row] = aR0.y;
    As[0][a_kv + 2][a_row] = aR0.z;  As[0][a_kv + 3][a_row] = aR0.w;
    As[0][a_kv + 0][a_row + 64] = aR1.x;  As[0][a_kv + 1][a_row + 64] = aR1.y;
    As[0][a_kv + 2][a_row + 64] = aR1.z;  As[0][a_kv + 3][a_row + 64] = aR1.w;
    if (BKM) {
        Bs[0][b_col + 0][b_row] = bR0.x;  Bs[0][b_col + 1][b_row] = bR0.y;
        Bs[0][b_col + 2][b_row] = bR0.z;  Bs[0][b_col + 3][b_row] = bR0.w;
        Bs[0][b_col + 0][b_row + 64] = bR1.x;  Bs[0][b_col + 1][b_row + 64] = bR1.y;
        Bs[0][b_col + 2][b_row + 64] = bR1.z;  Bs[0][b_col + 3][b_row + 64] = bR1.w;
    } else {
        *(float4*)&Bs[0][b_row][b_col]     = bR0;
        *(float4*)&Bs[0][b_row + 8][b_col] = bR1;
    }
    __syncthreads();

    for (int kt = 0; kt < nk; kt++) {
        const int buf = kt & 1;
        const bool more = (kt + 1) < nk;
        if (more) {
            const long long ko = (long long)(kt + 1) * BK;
            aR0 = *(const float4*)(Aptr + ko);
            aR1 = *(const float4*)(Aptr + ko + 64LL * K);
            if (BKM) {
                bR0 = *(const float4*)(Bptr + ko);
                bR1 = *(const float4*)(Bptr + ko + 64LL * K);
            } else {
                bR0 = *(const float4*)(Bptr + ko * N);
                bR1 = *(const float4*)(Bptr + ko * N + 8LL * N);
            }
        }

        #pragma unroll
        for (int kk = 0; kk < BK; kk++) {
            float4 a0 = *(const float4*)&As[buf][kk][ty * 4];
            float4 a1 = *(const float4*)&As[buf][kk][64 + ty * 4];
            float4 b0 = *(const float4*)&Bs[buf][kk][tx * 4];
            float4 b1 = *(const float4*)&Bs[buf][kk][64 + tx * 4];
            unsigned long long b2[4];
            b2[0] = pack2(b0.x, b0.y);
            b2[1] = pack2(b0.z, b0.w);
            b2[2] = pack2(b1.x, b1.y);
            b2[3] = pack2(b1.z, b1.w);
            float av[8] = {a0.x, a0.y, a0.z, a0.w, a1.x, a1.y, a1.z, a1.w};
            #pragma unroll
            for (int i = 0; i < 8; i++) {
                unsigned long long a2 = pack2(av[i], av[i]);
                #pragma unroll
                for (int j = 0; j < 4; j++)
                    acc[i][j] = fma2(a2, b2[j], acc[i][j]);
            }
        }

        if (more) {
            const int nb = buf ^ 1;
            As[nb][a_kv + 0][a_row] = aR0.x;  As[nb][a_kv + 1][a_row] = aR0.y;
            As[nb][a_kv + 2][a_row] = aR0.z;  As[nb][a_kv + 3][a_row] = aR0.w;
            As[nb][a_kv + 0][a_row + 64] = aR1.x;  As[nb][a_kv + 1][a_row + 64] = aR1.y;
            As[nb][a_kv + 2][a_row + 64] = aR1.z;  As[nb][a_kv + 3][a_row + 64] = aR1.w;
            if (BKM) {
                Bs[nb][b_col + 0][b_row] = bR0.x;  Bs[nb][b_col + 1][b_row] = bR0.y;
                Bs[nb][b_col + 2][b_row] = bR0.z;  Bs[nb][b_col + 3][b_row] = bR0.w;
                Bs[nb][b_col + 0][b_row + 64] = bR1.x;  Bs[nb][b_col + 1][b_row + 64] = bR1.y;
                Bs[nb][b_col + 2][b_row + 64] = bR1.z;  Bs[nb][b_col + 3][b_row + 64] = bR1.w;
            } else {
                *(float4*)&Bs[nb][b_row][b_col]     = bR0;
                *(float4*)&Bs[nb][b_row + 8][b_col] = bR1;
            }
            __syncthreads();
        }
    }

    // ---- epilogue ----
    const int row0 = m0 + ty * 4;
    const int col0 = n0 + tx * 4;
    float4 bv0 = make_float4(0.f, 0.f, 0.f, 0.f);
    float4 bv1 = make_float4(0.f, 0.f, 0.f, 0.f);
    if (BIAS) {
        bv0 = *(const float4*)&bias[col0];
        bv1 = *(const float4*)&bias[col0 + 64];
    }
    #pragma unroll
    for (int i = 0; i < 8; i++) {
        const int r = (i < 4) ? (row0 + i) : (row0 + 64 + (i - 4));
        float2 p0 = unpack2(acc[i][0]);
        float2 p1 = unpack2(acc[i][1]);
        float2 p2 = unpack2(acc[i][2]);
        float2 p3 = unpack2(acc[i][3]);
        float4 o0 = make_float4(p0.x, p0.y, p1.x, p1.y);
        float4 o1 = make_float4(p2.x, p2.y, p3.x, p3.y);
        if (BIAS) {
            o0.x += bv0.x; o0.y += bv0.y; o0.z += bv0.z; o0.w += bv0.w;
            o1.x += bv1.x; o1.y += bv1.y; o1.z += bv1.z; o1.w += bv1.w;
        }
        if (RELU) {
            o0.x = fmaxf(o0.x, 0.f); o0.y = fmaxf(o0.y, 0.f);
            o0.z = fmaxf(o0.z, 0.f); o0.w = fmaxf(o0.w, 0.f);
            o1.x = fmaxf(o1.x, 0.f); o1.y = fmaxf(o1.y, 0.f);
            o1.z = fmaxf(o1.z, 0.f); o1.w = fmaxf(o1.w, 0.f);
        }
        *(float4*)&C[(long long)r * N + col0]      = o0;
        *(float4*)&C[(long long)r * N + col0 + 64] = o1;
    }
}

// ---------------------------------------------------------------------------
// Row softmax over length 2048 (one CTA of 256 threads per row).
// ---------------------------------------------------------------------------
__global__ __launch_bounds__(256)
void softmax_kernel(float* __restrict__ att)
{
    float* row = att + (long long)blockIdx.x * 2048;
    const int tid = threadIdx.x;
    const int wid = tid >> 5, lane = tid & 31;

    float v[8];
    float m = -3.4e38f;
    #pragma unroll
    for (int i = 0; i < 8; i++) { v[i] = row[tid + 256 * i]; m = fmaxf(m, v[i]); }
    #pragma unroll
    for (int o = 16; o > 0; o >>= 1) m = fmaxf(m, __shfl_xor_sync(0xffffffffu, m, o));

    __shared__ float red[8];
    __shared__ float sval;
    if (lane == 0) red[wid] = m;
    __syncthreads();
    if (tid == 0) {
        float t = red[0];
        #pragma unroll
        for (int w = 1; w < 8; w++) t = fmaxf(t, red[w]);
        sval = t;
    }
    __syncthreads();
    m = sval;

    float s = 0.f;
    #pragma unroll
    for (int i = 0; i < 8; i++) { v[i] = expf(v[i] - m); s += v[i]; }
    #pragma unroll
    for (int o = 16; o > 0; o >>= 1) s += __shfl_xor_sync(0xffffffffu, s, o);
    __syncthreads();   // everyone has read sval / red before reuse
    if (lane == 0) red[wid] = s;
    __syncthreads();
    if (tid == 0) {
        float t = 0.f;
        #pragma unroll
        for (int w = 0; w < 8; w++) t += red[w];
        sval = 1.0f / t;
    }
    __syncthreads();
    const float inv = sval;
    #pragma unroll
    for (int i = 0; i < 8; i++) row[tid + 256 * i] = v[i] * inv;
}

// ---------------------------------------------------------------------------
extern "C" void kernel_launch(void* const* d_in, const int* in_sizes, int n_in,
                              void* d_out, int out_size)
{
    const float* proj_p = (const float*)d_in[0];   // [B, LP, H]
    const float* proj_q = (const float*)d_in[1];   // [B, LQ, H]
    const float* W      = (const float*)d_in[2];   // [H, H] (out, in)
    const float* bias   = (const float*)d_in[3];   // [H]
    float* out = (float*)d_out;                    // [B, LP, H]

    float *transq, *att, *attvec;
    cudaGetSymbolAddress((void**)&transq, g_transq);
    cudaGetSymbolAddress((void**)&att,    g_att);
    cudaGetSymbolAddress((void**)&attvec, g_attvec);

    const dim3 blk(256);

    // 1) trans_q = proj_q @ W^T + b          [B*LQ, H]
    sgemm_kernel<true, true, false><<<dim3(HID / BN, (BATCH * LQ) / BM, 1), blk>>>(
        proj_q, W, bias, transq, BATCH * LQ, HID, HID, 0, 0, 0);

    // 2) att[b] = proj_p[b] @ trans_q[b]^T   [LP, LQ] per batch
    sgemm_kernel<true, false, false><<<dim3(LQ / BN, LP / BM, BATCH), blk>>>(
        proj_p, transq, nullptr, att, LP, LQ, HID,
        (long long)LP * HID, (long long)LQ * HID, (long long)LP * LQ);

    // 3) softmax over last dim
    softmax_kernel<<<BATCH * LP, 256>>>(att);

    // 4) attvec[b] = att[b] @ proj_q[b]      [LP, H] per batch (B is n-major)
    sgemm_kernel<false, false, false><<<dim3(HID / BN, LP / BM, BATCH), blk>>>(
        att, proj_q, nullptr, attvec, LP, HID, LQ,
        (long long)LP * LQ, (long long)LQ * HID, (long long)LP * HID);

    // 5) out = relu(attvec @ W^T + b)        [B*LP, H]
    sgemm_kernel<true, true, true><<<dim3(HID / BN, (BATCH * LP) / BM, 1), blk>>>(
        attvec, W, bias, out, BATCH * LP, HID, HID, 0, 0, 0);
}

// round 4
// speedup vs baseline: 1.6976x; 1.6976x over previous
#include <cuda_runtime.h>
#include <cstdint>

#define BATCH 16
#define LP    2048
#define LQ    2048
#define HID   1024

#define TM 128
#define TN 128
#define KS 32
#define PITCH 40                 // uint16 elems per smem row (80 bytes)
#define STAGE_ELEMS (4 * 128 * PITCH)      // Ah, Al, Bh, Bl tiles
#define SMEM_BYTES  (2 * STAGE_ELEMS * 2)  // 2 stages, 2B/elem = 81920

// Scratch (allocation-free: __device__ globals)
__device__ float g_transq[(size_t)BATCH * LQ * HID];
__device__ float g_att   [(size_t)BATCH * LP * LQ];
__device__ float g_attvec[(size_t)BATCH * LP * HID];
__device__ float g_qT    [(size_t)BATCH * HID * LQ];

// ------------------------- helpers -------------------------
__device__ __forceinline__ uint32_t smem_u32(const void* p) {
    uint32_t a;
    asm("{ .reg .u64 t; cvta.to.shared.u64 t, %1; cvt.u32.u64 %0, t; }"
        : "=r"(a) : "l"(p));
    return a;
}

// d.hi16 = bf16(hi), d.lo16 = bf16(lo)
__device__ __forceinline__ uint32_t cvt_pair(float hi, float lo) {
    uint32_t r;
    asm("cvt.rn.bf16x2.f32 %0, %1, %2;" : "=r"(r) : "f"(hi), "f"(lo));
    return r;
}
__device__ __forceinline__ void sts64(uint32_t addr, uint32_t a, uint32_t b) {
    asm volatile("st.shared.v2.b32 [%0], {%1, %2};" :: "r"(addr), "r"(a), "r"(b) : "memory");
}

__device__ __forceinline__ void ldsm4(uint32_t* r, uint32_t addr) {
    asm volatile("ldmatrix.sync.aligned.m8n8.x4.shared.b16 {%0,%1,%2,%3}, [%4];"
                 : "=r"(r[0]), "=r"(r[1]), "=r"(r[2]), "=r"(r[3]) : "r"(addr));
}

__device__ __forceinline__ void mma16816(float* c, const uint32_t* a,
                                         uint32_t b0, uint32_t b1) {
    asm volatile(
        "mma.sync.aligned.m16n8k16.row.col.f32.bf16.bf16.f32 "
        "{%0,%1,%2,%3}, {%4,%5,%6,%7}, {%8,%9}, {%0,%1,%2,%3};"
        : "+f"(c[0]), "+f"(c[1]), "+f"(c[2]), "+f"(c[3])
        : "r"(a[0]), "r"(a[1]), "r"(a[2]), "r"(a[3]), "r"(b0), "r"(b1));
}

// split float4 into bf16 hi/lo quads, 8B store to each tile
__device__ __forceinline__ void split_store4(uint32_t hiAddr, uint32_t loAddr, float4 v) {
    uint32_t h01 = cvt_pair(v.y, v.x);
    uint32_t h23 = cvt_pair(v.w, v.z);
    float fx = __uint_as_float(h01 << 16);
    float fy = __uint_as_float(h01 & 0xffff0000u);
    float fz = __uint_as_float(h23 << 16);
    float fw = __uint_as_float(h23 & 0xffff0000u);
    uint32_t l01 = cvt_pair(v.y - fy, v.x - fx);
    uint32_t l23 = cvt_pair(v.w - fw, v.z - fz);
    sts64(hiAddr, h01, h23);
    sts64(loAddr, l01, l23);
}

// ---------------------------------------------------------------------------
// Split-bf16 HMMA GEMM: C[M,N] = A[M,K] * B^T (+bias)(+ReLU), fp32 I/O.
// A row-major [M,K] (k contiguous). B row-major [N,K] (k contiguous).
// Batched via blockIdx.z strides.
// ---------------------------------------------------------------------------
template <bool BIAS, bool RELU>
__global__ void __launch_bounds__(256, 1)
mm_hmma(const float* __restrict__ A, const float* __restrict__ Bg,
        const float* __restrict__ bias, float* __restrict__ C,
        int K, int lda, int ldb, int ldc,
        long long sA, long long sB, long long sC)
{
    extern __shared__ uint16_t sm[];
    const uint32_t smem = smem_u32(sm);

    const int tid  = threadIdx.x;
    const int lane = tid & 31;
    const int wid  = tid >> 5;
    const int wm   = wid & 3;        // 4 warps along M
    const int wn   = wid >> 2;       // 2 warps along N

    A  += sA * (long long)blockIdx.z;
    Bg += sB * (long long)blockIdx.z;
    C  += sC * (long long)blockIdx.z;
    const int m0 = blockIdx.y * TM;
    const int n0 = blockIdx.x * TN;

    // smem tile offsets (elements)
    const uint32_t OFF_AL = 128 * PITCH;
    const uint32_t OFF_BH = 2 * 128 * PITCH;
    const uint32_t OFF_BL = 3 * 128 * PITCH;

    // ---- gmem loader mapping: 128 rows x 32 k fp32 per operand per stage ----
    const int lrow = tid >> 1;          // 0..127
    const int lcol = (tid & 1) * 16;    // 0 or 16
    const float* pA = A  + (long long)(m0 + lrow) * lda + lcol;
    const float* pB = Bg + (long long)(n0 + lrow) * ldb + lcol;
    const uint32_t sOffBase = (uint32_t)(lrow * PITCH + lcol) * 2;  // bytes

    float4 va[4], vb[4];

    auto load_gmem = [&](int s) {
        const float* a = pA + (long long)s * KS;
        const float* b = pB + (long long)s * KS;
        #pragma unroll
        for (int i = 0; i < 4; i++) {
            va[i] = *(const float4*)(a + 4 * i);
            vb[i] = *(const float4*)(b + 4 * i);
        }
    };
    auto sts_stage = [&](int buf) {
        const uint32_t base = smem + (uint32_t)buf * STAGE_ELEMS * 2;
        #pragma unroll
        for (int i = 0; i < 4; i++) {
            const uint32_t o = sOffBase + i * 8;   // 4 elems = 8 bytes
            split_store4(base + o,                 base + OFF_AL * 2 + o, va[i]);
            split_store4(base + OFF_BH * 2 + o,    base + OFF_BL * 2 + o, vb[i]);
        }
    };

    // ---- fragment addresses ----
    const uint32_t a_r = (uint32_t)(wm * 32 + (lane & 15));
    const uint32_t a_c = (uint32_t)((lane >> 4) << 3);
    const uint32_t b_r = (uint32_t)(wn * 64 + (lane & 7) + ((lane & 16) >> 1));
    const uint32_t b_c = (uint32_t)(((lane >> 3) & 1) << 3);

    float acc[2][8][4];
    #pragma unroll
    for (int i = 0; i < 2; i++)
        #pragma unroll
        for (int j = 0; j < 8; j++)
            #pragma unroll
            for (int r = 0; r < 4; r++) acc[i][j][r] = 0.f;

    const int ns = K / KS;

    load_gmem(0);
    sts_stage(0);
    if (ns > 1) load_gmem(1);
    __syncthreads();

    for (int s = 0; s < ns; s++) {
        const uint32_t base = smem + (uint32_t)(s & 1) * STAGE_ELEMS * 2;
        #pragma unroll
        for (int kk2 = 0; kk2 < 2; kk2++) {
            const uint32_t kk = kk2 * 16;
            uint32_t ah[2][4], al[2][4], bh[4][4], bl[4][4];
            #pragma unroll
            for (int t = 0; t < 2; t++) {
                const uint32_t o = ((a_r + t * 16) * PITCH + kk + a_c) * 2;
                ldsm4(ah[t], base + o);
                ldsm4(al[t], base + OFF_AL * 2 + o);
            }
            #pragma unroll
            for (int t = 0; t < 4; t++) {
                const uint32_t o = ((b_r + t * 16) * PITCH + kk + b_c) * 2;
                ldsm4(bh[t], base + OFF_BH * 2 + o);
                ldsm4(bl[t], base + OFF_BL * 2 + o);
            }
            #pragma unroll
            for (int mi = 0; mi < 2; mi++)
                #pragma unroll
                for (int ni = 0; ni < 8; ni++) {
                    const int tb = ni >> 1, rb = (ni & 1) * 2;
                    mma16816(acc[mi][ni], ah[mi], bh[tb][rb], bh[tb][rb + 1]);
                    mma16816(acc[mi][ni], ah[mi], bl[tb][rb], bl[tb][rb + 1]);
                    mma16816(acc[mi][ni], al[mi], bh[tb][rb], bh[tb][rb + 1]);
                }
        }
        if (s + 1 < ns) {
            sts_stage((s + 1) & 1);
            __syncthreads();
            if (s + 2 < ns) load_gmem(s + 2);
        }
    }

    // ---- epilogue ----
    const int g  = lane >> 2;
    const int t4 = lane & 3;
    #pragma unroll
    for (int mi = 0; mi < 2; mi++) {
        #pragma unroll
        for (int ni = 0; ni < 8; ni++) {
            const int row = m0 + wm * 32 + mi * 16 + g;
            const int col = n0 + wn * 64 + ni * 8 + t4 * 2;
            float* c = acc[mi][ni];
            float b0 = 0.f, b1 = 0.f;
            if (BIAS) { b0 = __ldg(&bias[col]); b1 = __ldg(&bias[col + 1]); }
            float2 v0 = make_float2(c[0] + b0, c[1] + b1);
            float2 v1 = make_float2(c[2] + b0, c[3] + b1);
            if (RELU) {
                v0.x = fmaxf(v0.x, 0.f); v0.y = fmaxf(v0.y, 0.f);
                v1.x = fmaxf(v1.x, 0.f); v1.y = fmaxf(v1.y, 0.f);
            }
            *(float2*)&C[(long long)row * ldc + col]       = v0;
            *(float2*)&C[(long long)(row + 8) * ldc + col] = v1;
        }
    }
}

// ---------------------------------------------------------------------------
// Per-batch transpose: in [LQ, HID] -> out [HID, LQ]
// ---------------------------------------------------------------------------
__global__ __launch_bounds__(256)
void transpose_kernel(const float* __restrict__ in, float* __restrict__ out)
{
    __shared__ float t[32][33];
    const float* src = in  + (long long)blockIdx.z * LQ * HID;
    float*       dst = out + (long long)blockIdx.z * HID * LQ;
    const int h0 = blockIdx.x * 32;
    const int q0 = blockIdx.y * 32;
    const int tx = threadIdx.x, ty = threadIdx.y;
    #pragma unroll
    for (int j = 0; j < 4; j++)
        t[ty + 8 * j][tx] = src[(long long)(q0 + ty + 8 * j) * HID + h0 + tx];
    __syncthreads();
    #pragma unroll
    for (int j = 0; j < 4; j++)
        dst[(long long)(h0 + ty + 8 * j) * LQ + q0 + tx] = t[tx][ty + 8 * j];
}

// ---------------------------------------------------------------------------
// Row softmax over length 2048 (one CTA of 256 threads per row), in-place.
// ---------------------------------------------------------------------------
__global__ __launch_bounds__(256)
void softmax_kernel(float* __restrict__ att)
{
    float* row = att + (long long)blockIdx.x * 2048;
    const int tid = threadIdx.x;
    const int wid = tid >> 5, lane = tid & 31;

    float v[8];
    float m = -3.4e38f;
    #pragma unroll
    for (int i = 0; i < 8; i++) { v[i] = row[tid + 256 * i]; m = fmaxf(m, v[i]); }
    #pragma unroll
    for (int o = 16; o > 0; o >>= 1) m = fmaxf(m, __shfl_xor_sync(0xffffffffu, m, o));

    __shared__ float red[8];
    __shared__ float sval;
    if (lane == 0) red[wid] = m;
    __syncthreads();
    if (tid == 0) {
        float t = red[0];
        #pragma unroll
        for (int w = 1; w < 8; w++) t = fmaxf(t, red[w]);
        sval = t;
    }
    __syncthreads();
    m = sval;

    float s = 0.f;
    #pragma unroll
    for (int i = 0; i < 8; i++) { v[i] = expf(v[i] - m); s += v[i]; }
    #pragma unroll
    for (int o = 16; o > 0; o >>= 1) s += __shfl_xor_sync(0xffffffffu, s, o);
    __syncthreads();
    if (lane == 0) red[wid] = s;
    __syncthreads();
    if (tid == 0) {
        float t = 0.f;
        #pragma unroll
        for (int w = 0; w < 8; w++) t += red[w];
        sval = 1.0f / t;
    }
    __syncthreads();
    const float inv = sval;
    #pragma unroll
    for (int i = 0; i < 8; i++) row[tid + 256 * i] = v[i] * inv;
}

// ---------------------------------------------------------------------------
extern "C" void kernel_launch(void* const* d_in, const int* in_sizes, int n_in,
                              void* d_out, int out_size)
{
    const float* proj_p = (const float*)d_in[0];   // [B, LP, H]
    const float* proj_q = (const float*)d_in[1];   // [B, LQ, H]
    const float* W      = (const float*)d_in[2];   // [H, H]
    const float* bias   = (const float*)d_in[3];   // [H]
    float* out = (float*)d_out;                    // [B, LP, H]

    float *transq, *att, *attvec, *qT;
    cudaGetSymbolAddress((void**)&transq, g_transq);
    cudaGetSymbolAddress((void**)&att,    g_att);
    cudaGetSymbolAddress((void**)&attvec, g_attvec);
    cudaGetSymbolAddress((void**)&qT,     g_qT);

    cudaFuncSetAttribute(mm_hmma<true,  false>,
                         cudaFuncAttributeMaxDynamicSharedMemorySize, SMEM_BYTES);
    cudaFuncSetAttribute(mm_hmma<false, false>,
                         cudaFuncAttributeMaxDynamicSharedMemorySize, SMEM_BYTES);
    cudaFuncSetAttribute(mm_hmma<true,  true>,
                         cudaFuncAttributeMaxDynamicSharedMemorySize, SMEM_BYTES);

    const dim3 blk(256);

    // 0) qT[b] = proj_q[b]^T  (so GEMM 4's B operand is [N,K] k-contiguous)
    transpose_kernel<<<dim3(HID / 32, LQ / 32, BATCH), dim3(32, 8)>>>(proj_q, qT);

    // 1) trans_q = proj_q @ W^T + b        [B*LQ, H]
    mm_hmma<true, false><<<dim3(HID / TN, (BATCH * LQ) / TM, 1), blk, SMEM_BYTES>>>(
        proj_q, W, bias, transq, HID, HID, HID, HID, 0, 0, 0);

    // 2) att[b] = proj_p[b] @ trans_q[b]^T [LP, LQ] per batch
    mm_hmma<false, false><<<dim3(LQ / TN, LP / TM, BATCH), blk, SMEM_BYTES>>>(
        proj_p, transq, nullptr, att, HID, HID, HID, LQ,
        (long long)LP * HID, (long long)LQ * HID, (long long)LP * LQ);

    // 3) softmax over last dim
    softmax_kernel<<<BATCH * LP, 256>>>(att);

    // 4) attvec[b] = att[b] @ qT[b]^T      [LP, H] per batch
    mm_hmma<false, false><<<dim3(HID / TN, LP / TM, BATCH), blk, SMEM_BYTES>>>(
        att, qT, nullptr, attvec, LQ, LQ, LQ, HID,
        (long long)LP * LQ, (long long)HID * LQ, (long long)LP * HID);

    // 5) out = relu(attvec @ W^T + b)      [B*LP, H]
    mm_hmma<true, true><<<dim3(HID / TN, (BATCH * LP) / TM, 1), blk, SMEM_BYTES>>>(
        attvec, W, bias, out, HID, HID, HID, HID, 0, 0, 0);
}

// round 5
// speedup vs baseline: 1.7407x; 1.0254x over previous
#include <cuda_runtime.h>
#include <cuda_bf16.h>
#include <cstdint>

#define BATCH 16
#define LP    2048
#define LQ    2048
#define HID   1024

#define TM 128
#define TN 128
#define KS 32
#define PITCH 40                      // bf16 elems per smem row (80B)
#define TILE_B  (128 * PITCH * 2)     // 10240 B per tile
#define STAGE_B (4 * TILE_B)          // 40960 B per stage (Ah, Al, Bh, Bl)
#define NSTAGE 4
#define SMEM_BYTES (NSTAGE * STAGE_B) // 163840

typedef __nv_bfloat16 bf16;

// ---------------- persistent scratch (allocation-free) ----------------
__device__ __align__(256) bf16 g_ph [(size_t)BATCH * LP * HID];
__device__ __align__(256) bf16 g_pl [(size_t)BATCH * LP * HID];
__device__ __align__(256) bf16 g_qh [(size_t)BATCH * LQ * HID];
__device__ __align__(256) bf16 g_ql [(size_t)BATCH * LQ * HID];
__device__ __align__(256) bf16 g_qth[(size_t)BATCH * HID * LQ];
__device__ __align__(256) bf16 g_qtl[(size_t)BATCH * HID * LQ];
__device__ __align__(256) bf16 g_wh [(size_t)HID * HID];
__device__ __align__(256) bf16 g_wl [(size_t)HID * HID];
__device__ __align__(256) bf16 g_tqh[(size_t)BATCH * LQ * HID];
__device__ __align__(256) bf16 g_tql[(size_t)BATCH * LQ * HID];
__device__ __align__(256) float g_att[(size_t)BATCH * LP * LQ];
__device__ __align__(256) bf16 g_ah [(size_t)BATCH * LP * LQ];
__device__ __align__(256) bf16 g_al [(size_t)BATCH * LP * LQ];
__device__ __align__(256) bf16 g_vh [(size_t)BATCH * LP * HID];
__device__ __align__(256) bf16 g_vl [(size_t)BATCH * LP * HID];

// ------------------------- helpers -------------------------
__device__ __forceinline__ uint32_t smem_u32(const void* p) {
    uint32_t a;
    asm("{ .reg .u64 t; cvta.to.shared.u64 t, %1; cvt.u32.u64 %0, t; }"
        : "=r"(a) : "l"(p));
    return a;
}
// packs: upper16 = bf16(hi), lower16 = bf16(lo)
__device__ __forceinline__ uint32_t cvt_pair(float hi, float lo) {
    uint32_t r;
    asm("cvt.rn.bf16x2.f32 %0, %1, %2;" : "=r"(r) : "f"(hi), "f"(lo));
    return r;
}
__device__ __forceinline__ void ldsm4(uint32_t* r, uint32_t addr) {
    asm volatile("ldmatrix.sync.aligned.m8n8.x4.shared.b16 {%0,%1,%2,%3}, [%4];"
                 : "=r"(r[0]), "=r"(r[1]), "=r"(r[2]), "=r"(r[3]) : "r"(addr));
}
__device__ __forceinline__ void mma16816(float* c, const uint32_t* a,
                                         uint32_t b0, uint32_t b1) {
    asm volatile(
        "mma.sync.aligned.m16n8k16.row.col.f32.bf16.bf16.f32 "
        "{%0,%1,%2,%3}, {%4,%5,%6,%7}, {%8,%9}, {%0,%1,%2,%3};"
        : "+f"(c[0]), "+f"(c[1]), "+f"(c[2]), "+f"(c[3])
        : "r"(a[0]), "r"(a[1]), "r"(a[2]), "r"(a[3]), "r"(b0), "r"(b1));
}
__device__ __forceinline__ void cpasync16(uint32_t saddr, const void* g) {
    asm volatile("cp.async.cg.shared.global [%0], [%1], 16;"
                 :: "r"(saddr), "l"(g) : "memory");
}
// split two floats -> (hiWord, loWord) packed bf16x2
__device__ __forceinline__ void split2(float v0, float v1, uint32_t& h, uint32_t& l) {
    h = cvt_pair(v1, v0);
    float f0 = __uint_as_float(h << 16);
    float f1 = __uint_as_float(h & 0xffff0000u);
    l = cvt_pair(v1 - f1, v0 - f0);
}

// ---------------------------------------------------------------------------
// bf16x3 HMMA GEMM with cp.async loaders.
// C[M,N] = (Ah+Al)[M,K] * (Bh+Bl)[N,K]^T (+bias)(+ReLU)
// A,B pre-split bf16, row-major, k-contiguous. Output: fp32 or split bf16.
// ---------------------------------------------------------------------------
template <bool BIAS, bool RELU, bool OSPLIT>
__global__ void __launch_bounds__(256, 1)
mm_bf16x3(const bf16* __restrict__ Ah, const bf16* __restrict__ Al,
          const bf16* __restrict__ Bh, const bf16* __restrict__ Bl,
          const float* __restrict__ bias,
          float* __restrict__ Cf, bf16* __restrict__ Chi, bf16* __restrict__ Clo,
          int K, int lda, int ldb, int ldc,
          long long sA, long long sB, long long sC)
{
    extern __shared__ uint8_t sm[];
    const uint32_t smem = smem_u32(sm);
    const int tid  = threadIdx.x;
    const int lane = tid & 31;
    const int wid  = tid >> 5;
    const int wm   = wid & 3;
    const int wn   = wid >> 2;

    const long long zz = blockIdx.z;
    Ah += sA * zz;  Al += sA * zz;
    Bh += sB * zz;  Bl += sB * zz;
    if (OSPLIT) { Chi += sC * zz; Clo += sC * zz; }
    else        { Cf  += sC * zz; }

    const int m0 = blockIdx.y * TM;
    const int n0 = blockIdx.x * TN;

    // cp.async mapping: thread -> (row = tid>>2 [+64], 16B chunk = tid&3)
    const int crow = tid >> 2;
    const int ccol = (tid & 3) * 8;     // bf16 elems
    const bf16* gAh = Ah + (long long)(m0 + crow) * lda + ccol;
    const bf16* gAl = Al + (long long)(m0 + crow) * lda + ccol;
    const bf16* gBh = Bh + (long long)(n0 + crow) * ldb + ccol;
    const bf16* gBl = Bl + (long long)(n0 + crow) * ldb + ccol;
    const uint32_t sOff = (uint32_t)(crow * PITCH + ccol) * 2;

    const int ns = K / KS;

    auto issue = [&](int s) {
        if (s < ns) {
            const uint32_t b = smem + (uint32_t)(s & (NSTAGE - 1)) * STAGE_B;
            const long long ko = (long long)s * KS;
            #pragma unroll
            for (int i = 0; i < 2; i++) {
                const uint32_t so = sOff + (uint32_t)(i * 64 * PITCH * 2);
                cpasync16(b + so,              gAh + ko + (long long)i * 64 * lda);
                cpasync16(b + TILE_B + so,     gAl + ko + (long long)i * 64 * lda);
                cpasync16(b + 2 * TILE_B + so, gBh + ko + (long long)i * 64 * ldb);
                cpasync16(b + 3 * TILE_B + so, gBl + ko + (long long)i * 64 * ldb);
            }
        }
        asm volatile("cp.async.commit_group;" ::: "memory");
    };

    issue(0); issue(1); issue(2);

    // fragment coordinates
    const uint32_t a_r = (uint32_t)(wm * 32 + (lane & 15));
    const uint32_t a_c = (uint32_t)((lane >> 4) << 3);
    const uint32_t b_r = (uint32_t)(wn * 64 + (lane & 7) + ((lane & 16) >> 1));
    const uint32_t b_c = (uint32_t)(((lane >> 3) & 1) << 3);

    float acc[2][8][4];
    #pragma unroll
    for (int i = 0; i < 2; i++)
        #pragma unroll
        for (int j = 0; j < 8; j++)
            #pragma unroll
            for (int r = 0; r < 4; r++) acc[i][j][r] = 0.f;

    for (int s = 0; s < ns; s++) {
        asm volatile("cp.async.wait_group 2;" ::: "memory");
        __syncthreads();
        issue(s + 3);   // fills buffer freed at iter s-1 (all warps past sync)

        const uint32_t base = smem + (uint32_t)(s & (NSTAGE - 1)) * STAGE_B;
        #pragma unroll
        for (int kk2 = 0; kk2 < 2; kk2++) {
            const uint32_t kk = kk2 * 16;
            uint32_t ah[2][4], al[2][4], bh[4][4], bl[4][4];
            #pragma unroll
            for (int t = 0; t < 2; t++) {
                const uint32_t o = ((a_r + t * 16) * PITCH + kk + a_c) * 2;
                ldsm4(ah[t], base + o);
                ldsm4(al[t], base + TILE_B + o);
            }
            #pragma unroll
            for (int t = 0; t < 4; t++) {
                const uint32_t o = ((b_r + t * 16) * PITCH + kk + b_c) * 2;
                ldsm4(bh[t], base + 2 * TILE_B + o);
                ldsm4(bl[t], base + 3 * TILE_B + o);
            }
            #pragma unroll
            for (int mi = 0; mi < 2; mi++)
                #pragma unroll
                for (int ni = 0; ni < 8; ni++) {
                    const int tb = ni >> 1, rb = (ni & 1) * 2;
                    mma16816(acc[mi][ni], ah[mi], bh[tb][rb], bh[tb][rb + 1]);
                    mma16816(acc[mi][ni], ah[mi], bl[tb][rb], bl[tb][rb + 1]);
                    mma16816(acc[mi][ni], al[mi], bh[tb][rb], bh[tb][rb + 1]);
                }
        }
    }

    // ---- epilogue ----
    const int g  = lane >> 2;
    const int t4 = lane & 3;
    #pragma unroll
    for (int mi = 0; mi < 2; mi++) {
        #pragma unroll
        for (int ni = 0; ni < 8; ni++) {
            const int row = m0 + wm * 32 + mi * 16 + g;
            const int col = n0 + wn * 64 + ni * 8 + t4 * 2;
            float* c = acc[mi][ni];
            float b0 = 0.f, b1 = 0.f;
            if (BIAS) { b0 = __ldg(&bias[col]); b1 = __ldg(&bias[col + 1]); }
            float v00 = c[0] + b0, v01 = c[1] + b1;
            float v10 = c[2] + b0, v11 = c[3] + b1;
            if (RELU) {
                v00 = fmaxf(v00, 0.f); v01 = fmaxf(v01, 0.f);
                v10 = fmaxf(v10, 0.f); v11 = fmaxf(v11, 0.f);
            }
            if (OSPLIT) {
                uint32_t h, l;
                split2(v00, v01, h, l);
                ((uint32_t*)Chi)[((long long)row * ldc + col) >> 1] = h;
                ((uint32_t*)Clo)[((long long)row * ldc + col) >> 1] = l;
                split2(v10, v11, h, l);
                ((uint32_t*)Chi)[((long long)(row + 8) * ldc + col) >> 1] = h;
                ((uint32_t*)Clo)[((long long)(row + 8) * ldc + col) >> 1] = l;
            } else {
                *(float2*)&Cf[(long long)row * ldc + col]       = make_float2(v00, v01);
                *(float2*)&Cf[(long long)(row + 8) * ldc + col] = make_float2(v10, v11);
            }
        }
    }
}

// ---------------------------------------------------------------------------
// Elementwise split: fp32 -> bf16 hi/lo arrays
// ---------------------------------------------------------------------------
__global__ __launch_bounds__(256)
void split_kernel(const float* __restrict__ in, bf16* __restrict__ hi,
                  bf16* __restrict__ lo, long long n4)
{
    const long long stride = (long long)gridDim.x * blockDim.x;
    for (long long i = (long long)blockIdx.x * blockDim.x + threadIdx.x;
         i < n4; i += stride) {
        float4 v = ((const float4*)in)[i];
        uint32_t h01, l01, h23, l23;
        split2(v.x, v.y, h01, l01);
        split2(v.z, v.w, h23, l23);
        ((uint2*)hi)[i] = make_uint2(h01, h23);
        ((uint2*)lo)[i] = make_uint2(l01, l23);
    }
}

// ---------------------------------------------------------------------------
// Fused transpose+split: proj_q [LQ,H] fp32 -> qT hi/lo [H,LQ] bf16
// ---------------------------------------------------------------------------
__global__ __launch_bounds__(256)
void transsplit_kernel(const float* __restrict__ in,
                       bf16* __restrict__ hiOut, bf16* __restrict__ loOut)
{
    __shared__ float t[32][33];
    const float* src = in + (long long)blockIdx.z * LQ * HID;
    const long long obase = (long long)blockIdx.z * HID * LQ;
    const int h0 = blockIdx.x * 32;
    const int q0 = blockIdx.y * 32;
    const int tx = threadIdx.x, ty = threadIdx.y;
    #pragma unroll
    for (int j = 0; j < 4; j++)
        t[ty + 8 * j][tx] = src[(long long)(q0 + ty + 8 * j) * HID + h0 + tx];
    __syncthreads();
    const int p    = tx & 15;
    const int half = tx >> 4;   // 0: hi array, 1: lo array
    #pragma unroll
    for (int j = 0; j < 4; j++) {
        const int hrow = h0 + ty + 8 * j;
        float v0 = t[2 * p][ty + 8 * j];
        float v1 = t[2 * p + 1][ty + 8 * j];
        uint32_t h, l;
        split2(v0, v1, h, l);
        uint32_t* dst = (uint32_t*)(half ? loOut : hiOut);
        dst[(obase + (long long)hrow * LQ + q0) / 2 + p] = half ? l : h;
    }
}

// ---------------------------------------------------------------------------
// Row softmax (2048) reading fp32, writing split bf16 hi/lo.
// ---------------------------------------------------------------------------
__global__ __launch_bounds__(256)
void softmax_split(const float* __restrict__ att,
                   bf16* __restrict__ oh, bf16* __restrict__ ol)
{
    const float* row = att + (long long)blockIdx.x * 2048;
    uint32_t* oh32 = (uint32_t*)oh + (long long)blockIdx.x * 1024;
    uint32_t* ol32 = (uint32_t*)ol + (long long)blockIdx.x * 1024;
    const int tid = threadIdx.x;
    const int wid = tid >> 5, lane = tid & 31;

    float2 v[4];
    float m = -3.4e38f;
    #pragma unroll
    for (int i = 0; i < 4; i++) {
        v[i] = ((const float2*)row)[tid + 256 * i];
        m = fmaxf(m, fmaxf(v[i].x, v[i].y));
    }
    #pragma unroll
    for (int o = 16; o > 0; o >>= 1) m = fmaxf(m, __shfl_xor_sync(0xffffffffu, m, o));

    __shared__ float red[8];
    __shared__ float sval;
    if (lane == 0) red[wid] = m;
    __syncthreads();
    if (tid == 0) {
        float t = red[0];
        #pragma unroll
        for (int w = 1; w < 8; w++) t = fmaxf(t, red[w]);
        sval = t;
    }
    __syncthreads();
    m = sval;

    float s = 0.f;
    #pragma unroll
    for (int i = 0; i < 4; i++) {
        v[i].x = expf(v[i].x - m);
        v[i].y = expf(v[i].y - m);
        s += v[i].x + v[i].y;
    }
    #pragma unroll
    for (int o = 16; o > 0; o >>= 1) s += __shfl_xor_sync(0xffffffffu, s, o);
    __syncthreads();
    if (lane == 0) red[wid] = s;
    __syncthreads();
    if (tid == 0) {
        float t = 0.f;
        #pragma unroll
        for (int w = 0; w < 8; w++) t += red[w];
        sval = 1.0f / t;
    }
    __syncthreads();
    const float inv = sval;
    #pragma unroll
    for (int i = 0; i < 4; i++) {
        float x = v[i].x * inv, y = v[i].y * inv;
        uint32_t h, l;
        split2(x, y, h, l);
        oh32[tid + 256 * i] = h;
        ol32[tid + 256 * i] = l;
    }
}

// ---------------------------------------------------------------------------
extern "C" void kernel_launch(void* const* d_in, const int* in_sizes, int n_in,
                              void* d_out, int out_size)
{
    const float* proj_p = (const float*)d_in[0];   // [B, LP, H]
    const float* proj_q = (const float*)d_in[1];   // [B, LQ, H]
    const float* W      = (const float*)d_in[2];   // [H, H]
    const float* bias   = (const float*)d_in[3];   // [H]
    float* out = (float*)d_out;                    // [B, LP, H]

    bf16 *ph, *pl, *qh, *ql, *qth, *qtl, *wh, *wl, *tqh, *tql, *ah, *al, *vh, *vl;
    float *att;
    cudaGetSymbolAddress((void**)&ph,  g_ph);   cudaGetSymbolAddress((void**)&pl,  g_pl);
    cudaGetSymbolAddress((void**)&qh,  g_qh);   cudaGetSymbolAddress((void**)&ql,  g_ql);
    cudaGetSymbolAddress((void**)&qth, g_qth);  cudaGetSymbolAddress((void**)&qtl, g_qtl);
    cudaGetSymbolAddress((void**)&wh,  g_wh);   cudaGetSymbolAddress((void**)&wl,  g_wl);
    cudaGetSymbolAddress((void**)&tqh, g_tqh);  cudaGetSymbolAddress((void**)&tql, g_tql);
    cudaGetSymbolAddress((void**)&ah,  g_ah);   cudaGetSymbolAddress((void**)&al,  g_al);
    cudaGetSymbolAddress((void**)&vh,  g_vh);   cudaGetSymbolAddress((void**)&vl,  g_vl);
    cudaGetSymbolAddress((void**)&att, g_att);

    cudaFuncSetAttribute(mm_bf16x3<true,  false, true >,
                         cudaFuncAttributeMaxDynamicSharedMemorySize, SMEM_BYTES);
    cudaFuncSetAttribute(mm_bf16x3<false, false, false>,
                         cudaFuncAttributeMaxDynamicSharedMemorySize, SMEM_BYTES);
    cudaFuncSetAttribute(mm_bf16x3<false, false, true >,
                         cudaFuncAttributeMaxDynamicSharedMemorySize, SMEM_BYTES);
    cudaFuncSetAttribute(mm_bf16x3<true,  true,  false>,
                         cudaFuncAttributeMaxDynamicSharedMemorySize, SMEM_BYTES);

    const dim3 blk(256);

    // 0) operand splits
    split_kernel<<<8192, 256>>>(proj_p, ph, pl, (long long)BATCH * LP * HID / 4);
    split_kernel<<<8192, 256>>>(proj_q, qh, ql, (long long)BATCH * LQ * HID / 4);
    split_kernel<<<1024, 256>>>(W, wh, wl, (long long)HID * HID / 4);
    transsplit_kernel<<<dim3(HID / 32, LQ / 32, BATCH), dim3(32, 8)>>>(proj_q, qth, qtl);

    // 1) trans_q = proj_q @ W^T + b  -> split bf16 [B*LQ, H]
    mm_bf16x3<true, false, true><<<dim3(HID / TN, (BATCH * LQ) / TM, 1), blk, SMEM_BYTES>>>(
        qh, ql, wh, wl, bias, nullptr, tqh, tql, HID, HID, HID, HID, 0, 0, 0);

    // 2) att[b] = proj_p[b] @ trans_q[b]^T  -> fp32 [LP, LQ]
    mm_bf16x3<false, false, false><<<dim3(LQ / TN, LP / TM, BATCH), blk, SMEM_BYTES>>>(
        ph, pl, tqh, tql, nullptr, att, nullptr, nullptr, HID, HID, HID, LQ,
        (long long)LP * HID, (long long)LQ * HID, (long long)LP * LQ);

    // 3) softmax -> split bf16
    softmax_split<<<BATCH * LP, 256>>>(att, ah, al);

    // 4) attvec[b] = att[b] @ qT[b]^T  -> split bf16 [LP, H]
    mm_bf16x3<false, false, true><<<dim3(HID / TN, LP / TM, BATCH), blk, SMEM_BYTES>>>(
        ah, al, qth, qtl, nullptr, nullptr, vh, vl, LQ, LQ, LQ, HID,
        (long long)LP * LQ, (long long)HID * LQ, (long long)LP * HID);

    // 5) out = relu(attvec @ W^T + b)  -> fp32 [B*LP, H]
    mm_bf16x3<true, true, false><<<dim3(HID / TN, (BATCH * LP) / TM, 1), blk, SMEM_BYTES>>>(
        vh, vl, wh, wl, bias, out, nullptr, nullptr, HID, HID, HID, HID, 0, 0, 0);
}

// round 6
// speedup vs baseline: 2.0449x; 1.1748x over previous
#include <cuda_runtime.h>
#include <cuda_bf16.h>
#include <cstdint>

#define BATCH 16
#define LP    2048
#define LQ    2048
#define HID   1024

#define TM 128
#define TN 128
#define KS 32
#define PITCH 40                      // bf16 elems per smem row (80B)
#define TILE_B  (128 * PITCH * 2)     // 10240 B per tile
#define STAGE_B (4 * TILE_B)          // 40960 B per stage (Ah, Al, Bh, Bl)
#define NSTAGE 2
#define SMEM_BYTES (NSTAGE * STAGE_B) // 81920 -> 2 CTAs/SM

typedef __nv_bfloat16 bf16;

// ---------------- persistent scratch (allocation-free) ----------------
__device__ __align__(256) bf16 g_ph [(size_t)BATCH * LP * HID];
__device__ __align__(256) bf16 g_pl [(size_t)BATCH * LP * HID];
__device__ __align__(256) bf16 g_qh [(size_t)BATCH * LQ * HID];
__device__ __align__(256) bf16 g_ql [(size_t)BATCH * LQ * HID];
__device__ __align__(256) bf16 g_qth[(size_t)BATCH * HID * LQ];
__device__ __align__(256) bf16 g_qtl[(size_t)BATCH * HID * LQ];
__device__ __align__(256) bf16 g_wh [(size_t)HID * HID];
__device__ __align__(256) bf16 g_wl [(size_t)HID * HID];
__device__ __align__(256) bf16 g_tqh[(size_t)BATCH * LQ * HID];
__device__ __align__(256) bf16 g_tql[(size_t)BATCH * LQ * HID];
__device__ __align__(256) float g_att[(size_t)BATCH * LP * LQ];
__device__ __align__(256) bf16 g_ah [(size_t)BATCH * LP * LQ];
__device__ __align__(256) bf16 g_al [(size_t)BATCH * LP * LQ];
__device__ __align__(256) bf16 g_vh [(size_t)BATCH * LP * HID];
__device__ __align__(256) bf16 g_vl [(size_t)BATCH * LP * HID];

// ------------------------- helpers -------------------------
__device__ __forceinline__ uint32_t smem_u32(const void* p) {
    uint32_t a;
    asm("{ .reg .u64 t; cvta.to.shared.u64 t, %1; cvt.u32.u64 %0, t; }"
        : "=r"(a) : "l"(p));
    return a;
}
// packs: upper16 = bf16(hi), lower16 = bf16(lo)
__device__ __forceinline__ uint32_t cvt_pair(float hi, float lo) {
    uint32_t r;
    asm("cvt.rn.bf16x2.f32 %0, %1, %2;" : "=r"(r) : "f"(hi), "f"(lo));
    return r;
}
__device__ __forceinline__ void ldsm4(uint32_t* r, uint32_t addr) {
    asm volatile("ldmatrix.sync.aligned.m8n8.x4.shared.b16 {%0,%1,%2,%3}, [%4];"
                 : "=r"(r[0]), "=r"(r[1]), "=r"(r[2]), "=r"(r[3]) : "r"(addr));
}
__device__ __forceinline__ void mma16816(float* c, const uint32_t* a,
                                         uint32_t b0, uint32_t b1) {
    asm volatile(
        "mma.sync.aligned.m16n8k16.row.col.f32.bf16.bf16.f32 "
        "{%0,%1,%2,%3}, {%4,%5,%6,%7}, {%8,%9}, {%0,%1,%2,%3};"
        : "+f"(c[0]), "+f"(c[1]), "+f"(c[2]), "+f"(c[3])
        : "r"(a[0]), "r"(a[1]), "r"(a[2]), "r"(a[3]), "r"(b0), "r"(b1));
}
__device__ __forceinline__ void cpasync16(uint32_t saddr, const void* g) {
    asm volatile("cp.async.cg.shared.global [%0], [%1], 16;"
                 :: "r"(saddr), "l"(g) : "memory");
}
// split two floats -> (hiWord, loWord) packed bf16x2
__device__ __forceinline__ void split2(float v0, float v1, uint32_t& h, uint32_t& l) {
    h = cvt_pair(v1, v0);
    float f0 = __uint_as_float(h << 16);
    float f1 = __uint_as_float(h & 0xffff0000u);
    l = cvt_pair(v1 - f1, v0 - f0);
}

// ---------------------------------------------------------------------------
// bf16x3 HMMA GEMM, cp.async double-buffer, 2 CTAs/SM.
// C[M,N] = (Ah+Al)[M,K] * (Bh+Bl)[N,K]^T (+bias)(+ReLU)
// ---------------------------------------------------------------------------
template <bool BIAS, bool RELU, bool OSPLIT>
__global__ void __launch_bounds__(256, 2)
mm_bf16x3(const bf16* __restrict__ Ah, const bf16* __restrict__ Al,
          const bf16* __restrict__ Bh, const bf16* __restrict__ Bl,
          const float* __restrict__ bias,
          float* __restrict__ Cf, bf16* __restrict__ Chi, bf16* __restrict__ Clo,
          int K, int lda, int ldb, int ldc,
          long long sA, long long sB, long long sC)
{
    extern __shared__ uint8_t sm[];
    const uint32_t smem = smem_u32(sm);
    const int tid  = threadIdx.x;
    const int lane = tid & 31;
    const int wid  = tid >> 5;
    const int wm   = wid & 3;
    const int wn   = wid >> 2;

    const long long zz = blockIdx.z;
    Ah += sA * zz;  Al += sA * zz;
    Bh += sB * zz;  Bl += sB * zz;
    if (OSPLIT) { Chi += sC * zz; Clo += sC * zz; }
    else        { Cf  += sC * zz; }

    const int m0 = blockIdx.y * TM;
    const int n0 = blockIdx.x * TN;

    // cp.async mapping
    const int crow = tid >> 2;
    const int ccol = (tid & 3) * 8;
    const bf16* gAh = Ah + (long long)(m0 + crow) * lda + ccol;
    const bf16* gAl = Al + (long long)(m0 + crow) * lda + ccol;
    const bf16* gBh = Bh + (long long)(n0 + crow) * ldb + ccol;
    const bf16* gBl = Bl + (long long)(n0 + crow) * ldb + ccol;
    const uint32_t sOff = (uint32_t)(crow * PITCH + ccol) * 2;

    const int ns = K / KS;

    auto issue = [&](int s) {
        if (s < ns) {
            const uint32_t b = smem + (uint32_t)(s & (NSTAGE - 1)) * STAGE_B;
            const long long ko = (long long)s * KS;
            #pragma unroll
            for (int i = 0; i < 2; i++) {
                const uint32_t so = sOff + (uint32_t)(i * 64 * PITCH * 2);
                cpasync16(b + so,              gAh + ko + (long long)i * 64 * lda);
                cpasync16(b + TILE_B + so,     gAl + ko + (long long)i * 64 * lda);
                cpasync16(b + 2 * TILE_B + so, gBh + ko + (long long)i * 64 * ldb);
                cpasync16(b + 3 * TILE_B + so, gBl + ko + (long long)i * 64 * ldb);
            }
        }
        asm volatile("cp.async.commit_group;" ::: "memory");
    };

    issue(0); issue(1);

    // fragment coordinates
    const uint32_t a_r = (uint32_t)(wm * 32 + (lane & 15));
    const uint32_t a_c = (uint32_t)((lane >> 4) << 3);
    const uint32_t b_r = (uint32_t)(wn * 64 + (lane & 7) + ((lane & 16) >> 1));
    const uint32_t b_c = (uint32_t)(((lane >> 3) & 1) << 3);

    float acc[2][8][4];
    #pragma unroll
    for (int i = 0; i < 2; i++)
        #pragma unroll
        for (int j = 0; j < 8; j++)
            #pragma unroll
            for (int r = 0; r < 4; r++) acc[i][j][r] = 0.f;

    for (int s = 0; s < ns; s++) {
        asm volatile("cp.async.wait_group 1;" ::: "memory");
        __syncthreads();

        const uint32_t base = smem + (uint32_t)(s & (NSTAGE - 1)) * STAGE_B;
        #pragma unroll
        for (int kk2 = 0; kk2 < 2; kk2++) {
            const uint32_t kk = kk2 * 16;
            uint32_t ah[2][4], al[2][4];
            #pragma unroll
            for (int t = 0; t < 2; t++) {
                const uint32_t o = ((a_r + t * 16) * PITCH + kk + a_c) * 2;
                ldsm4(ah[t], base + o);
                ldsm4(al[t], base + TILE_B + o);
            }
            #pragma unroll
            for (int tb = 0; tb < 4; tb++) {
                uint32_t bh[4], bl[4];
                const uint32_t o = ((b_r + tb * 16) * PITCH + kk + b_c) * 2;
                ldsm4(bh, base + 2 * TILE_B + o);
                ldsm4(bl, base + 3 * TILE_B + o);
                #pragma unroll
                for (int mi = 0; mi < 2; mi++) {
                    mma16816(acc[mi][2 * tb],     ah[mi], bh[0], bh[1]);
                    mma16816(acc[mi][2 * tb],     ah[mi], bl[0], bl[1]);
                    mma16816(acc[mi][2 * tb],     al[mi], bh[0], bh[1]);
                    mma16816(acc[mi][2 * tb + 1], ah[mi], bh[2], bh[3]);
                    mma16816(acc[mi][2 * tb + 1], ah[mi], bl[2], bl[3]);
                    mma16816(acc[mi][2 * tb + 1], al[mi], bh[2], bh[3]);
                }
            }
        }
        __syncthreads();
        issue(s + 2);   // buffer s%2 free: all warps done reading it
    }

    // ---- epilogue ----
    const int g  = lane >> 2;
    const int t4 = lane & 3;
    #pragma unroll
    for (int mi = 0; mi < 2; mi++) {
        #pragma unroll
        for (int ni = 0; ni < 8; ni++) {
            const int row = m0 + wm * 32 + mi * 16 + g;
            const int col = n0 + wn * 64 + ni * 8 + t4 * 2;
            float* c = acc[mi][ni];
            float b0 = 0.f, b1 = 0.f;
            if (BIAS) { b0 = __ldg(&bias[col]); b1 = __ldg(&bias[col + 1]); }
            float v00 = c[0] + b0, v01 = c[1] + b1;
            float v10 = c[2] + b0, v11 = c[3] + b1;
            if (RELU) {
                v00 = fmaxf(v00, 0.f); v01 = fmaxf(v01, 0.f);
                v10 = fmaxf(v10, 0.f); v11 = fmaxf(v11, 0.f);
            }
            if (OSPLIT) {
                uint32_t h, l;
                split2(v00, v01, h, l);
                ((uint32_t*)Chi)[((long long)row * ldc + col) >> 1] = h;
                ((uint32_t*)Clo)[((long long)row * ldc + col) >> 1] = l;
                split2(v10, v11, h, l);
                ((uint32_t*)Chi)[((long long)(row + 8) * ldc + col) >> 1] = h;
                ((uint32_t*)Clo)[((long long)(row + 8) * ldc + col) >> 1] = l;
            } else {
                *(float2*)&Cf[(long long)row * ldc + col]       = make_float2(v00, v01);
                *(float2*)&Cf[(long long)(row + 8) * ldc + col] = make_float2(v10, v11);
            }
        }
    }
}

// ---------------------------------------------------------------------------
// Elementwise split: fp32 -> bf16 hi/lo arrays
// ---------------------------------------------------------------------------
__global__ __launch_bounds__(256)
void split_kernel(const float* __restrict__ in, bf16* __restrict__ hi,
                  bf16* __restrict__ lo, long long n4)
{
    const long long stride = (long long)gridDim.x * blockDim.x;
    for (long long i = (long long)blockIdx.x * blockDim.x + threadIdx.x;
         i < n4; i += stride) {
        float4 v = ((const float4*)in)[i];
        uint32_t h01, l01, h23, l23;
        split2(v.x, v.y, h01, l01);
        split2(v.z, v.w, h23, l23);
        ((uint2*)hi)[i] = make_uint2(h01, h23);
        ((uint2*)lo)[i] = make_uint2(l01, l23);
    }
}

// ---------------------------------------------------------------------------
// Fused transpose+split: proj_q [LQ,H] fp32 -> qT hi/lo [H,LQ] bf16
// ---------------------------------------------------------------------------
__global__ __launch_bounds__(256)
void transsplit_kernel(const float* __restrict__ in,
                       bf16* __restrict__ hiOut, bf16* __restrict__ loOut)
{
    __shared__ float t[32][33];
    const float* src = in + (long long)blockIdx.z * LQ * HID;
    const long long obase = (long long)blockIdx.z * HID * LQ;
    const int h0 = blockIdx.x * 32;
    const int q0 = blockIdx.y * 32;
    const int tx = threadIdx.x, ty = threadIdx.y;
    #pragma unroll
    for (int j = 0; j < 4; j++)
        t[ty + 8 * j][tx] = src[(long long)(q0 + ty + 8 * j) * HID + h0 + tx];
    __syncthreads();
    const int p    = tx & 15;
    const int half = tx >> 4;
    #pragma unroll
    for (int j = 0; j < 4; j++) {
        const int hrow = h0 + ty + 8 * j;
        float v0 = t[2 * p][ty + 8 * j];
        float v1 = t[2 * p + 1][ty + 8 * j];
        uint32_t h, l;
        split2(v0, v1, h, l);
        uint32_t* dst = (uint32_t*)(half ? loOut : hiOut);
        dst[(obase + (long long)hrow * LQ + q0) / 2 + p] = half ? l : h;
    }
}

// ---------------------------------------------------------------------------
// Row softmax (2048) reading fp32, writing split bf16 hi/lo.
// ---------------------------------------------------------------------------
__global__ __launch_bounds__(256)
void softmax_split(const float* __restrict__ att,
                   bf16* __restrict__ oh, bf16* __restrict__ ol)
{
    const float* row = att + (long long)blockIdx.x * 2048;
    uint32_t* oh32 = (uint32_t*)oh + (long long)blockIdx.x * 1024;
    uint32_t* ol32 = (uint32_t*)ol + (long long)blockIdx.x * 1024;
    const int tid = threadIdx.x;
    const int wid = tid >> 5, lane = tid & 31;

    float2 v[4];
    float m = -3.4e38f;
    #pragma unroll
    for (int i = 0; i < 4; i++) {
        v[i] = ((const float2*)row)[tid + 256 * i];
        m = fmaxf(m, fmaxf(v[i].x, v[i].y));
    }
    #pragma unroll
    for (int o = 16; o > 0; o >>= 1) m = fmaxf(m, __shfl_xor_sync(0xffffffffu, m, o));

    __shared__ float red[8];
    __shared__ float sval;
    if (lane == 0) red[wid] = m;
    __syncthreads();
    if (tid == 0) {
        float t = red[0];
        #pragma unroll
        for (int w = 1; w < 8; w++) t = fmaxf(t, red[w]);
        sval = t;
    }
    __syncthreads();
    m = sval;

    float s = 0.f;
    #pragma unroll
    for (int i = 0; i < 4; i++) {
        v[i].x = expf(v[i].x - m);
        v[i].y = expf(v[i].y - m);
        s += v[i].x + v[i].y;
    }
    #pragma unroll
    for (int o = 16; o > 0; o >>= 1) s += __shfl_xor_sync(0xffffffffu, s, o);
    __syncthreads();
    if (lane == 0) red[wid] = s;
    __syncthreads();
    if (tid == 0) {
        float t = 0.f;
        #pragma unroll
        for (int w = 0; w < 8; w++) t += red[w];
        sval = 1.0f / t;
    }
    __syncthreads();
    const float inv = sval;
    #pragma unroll
    for (int i = 0; i < 4; i++) {
        float x = v[i].x * inv, y = v[i].y * inv;
        uint32_t h, l;
        split2(x, y, h, l);
        oh32[tid + 256 * i] = h;
        ol32[tid + 256 * i] = l;
    }
}

// ---------------------------------------------------------------------------
extern "C" void kernel_launch(void* const* d_in, const int* in_sizes, int n_in,
                              void* d_out, int out_size)
{
    const float* proj_p = (const float*)d_in[0];   // [B, LP, H]
    const float* proj_q = (const float*)d_in[1];   // [B, LQ, H]
    const float* W      = (const float*)d_in[2];   // [H, H]
    const float* bias   = (const float*)d_in[3];   // [H]
    float* out = (float*)d_out;                    // [B, LP, H]

    bf16 *ph, *pl, *qh, *ql, *qth, *qtl, *wh, *wl, *tqh, *tql, *ah, *al, *vh, *vl;
    float *att;
    cudaGetSymbolAddress((void**)&ph,  g_ph);   cudaGetSymbolAddress((void**)&pl,  g_pl);
    cudaGetSymbolAddress((void**)&qh,  g_qh);   cudaGetSymbolAddress((void**)&ql,  g_ql);
    cudaGetSymbolAddress((void**)&qth, g_qth);  cudaGetSymbolAddress((void**)&qtl, g_qtl);
    cudaGetSymbolAddress((void**)&wh,  g_wh);   cudaGetSymbolAddress((void**)&wl,  g_wl);
    cudaGetSymbolAddress((void**)&tqh, g_tqh);  cudaGetSymbolAddress((void**)&tql, g_tql);
    cudaGetSymbolAddress((void**)&ah,  g_ah);   cudaGetSymbolAddress((void**)&al,  g_al);
    cudaGetSymbolAddress((void**)&vh,  g_vh);   cudaGetSymbolAddress((void**)&vl,  g_vl);
    cudaGetSymbolAddress((void**)&att, g_att);

    cudaFuncSetAttribute(mm_bf16x3<true,  false, true >,
                         cudaFuncAttributeMaxDynamicSharedMemorySize, SMEM_BYTES);
    cudaFuncSetAttribute(mm_bf16x3<false, false, false>,
                         cudaFuncAttributeMaxDynamicSharedMemorySize, SMEM_BYTES);
    cudaFuncSetAttribute(mm_bf16x3<false, false, true >,
                         cudaFuncAttributeMaxDynamicSharedMemorySize, SMEM_BYTES);
    cudaFuncSetAttribute(mm_bf16x3<true,  true,  false>,
                         cudaFuncAttributeMaxDynamicSharedMemorySize, SMEM_BYTES);

    const dim3 blk(256);

    // 0) operand splits
    split_kernel<<<8192, 256>>>(proj_p, ph, pl, (long long)BATCH * LP * HID / 4);
    split_kernel<<<8192, 256>>>(proj_q, qh, ql, (long long)BATCH * LQ * HID / 4);
    split_kernel<<<1024, 256>>>(W, wh, wl, (long long)HID * HID / 4);
    transsplit_kernel<<<dim3(HID / 32, LQ / 32, BATCH), dim3(32, 8)>>>(proj_q, qth, qtl);

    // 1) trans_q = proj_q @ W^T + b  -> split bf16 [B*LQ, H]
    mm_bf16x3<true, false, true><<<dim3(HID / TN, (BATCH * LQ) / TM, 1), blk, SMEM_BYTES>>>(
        qh, ql, wh, wl, bias, nullptr, tqh, tql, HID, HID, HID, HID, 0, 0, 0);

    // 2) att[b] = proj_p[b] @ trans_q[b]^T  -> fp32 [LP, LQ]
    mm_bf16x3<false, false, false><<<dim3(LQ / TN, LP / TM, BATCH), blk, SMEM_BYTES>>>(
        ph, pl, tqh, tql, nullptr, att, nullptr, nullptr, HID, HID, HID, LQ,
        (long long)LP * HID, (long long)LQ * HID, (long long)LP * LQ);

    // 3) softmax -> split bf16
    softmax_split<<<BATCH * LP, 256>>>(att, ah, al);

    // 4) attvec[b] = att[b] @ qT[b]^T  -> split bf16 [LP, H]
    mm_bf16x3<false, false, true><<<dim3(HID / TN, LP / TM, BATCH), blk, SMEM_BYTES>>>(
        ah, al, qth, qtl, nullptr, nullptr, vh, vl, LQ, LQ, LQ, HID,
        (long long)LP * LQ, (long long)HID * LQ, (long long)LP * HID);

    // 5) out = relu(attvec @ W^T + b)  -> fp32 [B*LP, H]
    mm_bf16x3<true, true, false><<<dim3(HID / TN, (BATCH * LP) / TM, 1), blk, SMEM_BYTES>>>(
        vh, vl, wh, wl, bias, out, nullptr, nullptr, HID, HID, HID, HID, 0, 0, 0);
}